// round 12
// baseline (speedup 1.0000x reference)
#include <cuda_runtime.h>
#include <cuda_fp16.h>
#include <cstdint>

#define HEADS   16
#define HDIM    64
#define NK      2048
#define NSLOT   35
#define NQROWS  122880     // 20*2048 + 10*4096 + 5*8192
// 0.125 (d^-0.5) * log2(e) folded into Q so softmax is exp2(s)
#define QSCALE_LOG2E 0.1803368801111f

__device__ __half g_Q[NQROWS * HDIM];
__device__ __half g_K[NSLOT * NK * HDIM];
__device__ __half g_V[NSLOT * HDIM * NK];

// smem: Q[128][64] fp16 (16KB) | K x3 [128][64] (48KB) | Vt x3 [64][128] (48KB)
#define QS_OFF    0
#define KS_OFF(b) (16384 + (b) * 16384)
#define VS_OFF(b) (65536 + (b) * 16384)
#define SMEM_BYTES 114688

// ---------------- PTX helpers ----------------
__device__ __forceinline__ uint32_t smem_u32(const void* p) {
    uint32_t a;
    asm("{ .reg .u64 t; cvta.to.shared.u64 t, %1; cvt.u32.u64 %0, t; }" : "=r"(a) : "l"(p));
    return a;
}
#define CP_ASYNC16(dst, src) \
    asm volatile("cp.async.cg.shared.global [%0], [%1], 16;" :: "r"(dst), "l"(src) : "memory")
#define CP_COMMIT()  asm volatile("cp.async.commit_group;" ::: "memory")
#define CP_WAIT_1()  asm volatile("cp.async.wait_group 1;" ::: "memory")
#define CP_WAIT_0()  asm volatile("cp.async.wait_group 0;" ::: "memory")

#define LDSM_X4(r0, r1, r2, r3, addr) \
    asm volatile("ldmatrix.sync.aligned.m8n8.x4.shared.b16 {%0,%1,%2,%3}, [%4];" \
        : "=r"(r0), "=r"(r1), "=r"(r2), "=r"(r3) : "r"(addr))

#define MMA_FP16(c, a, b0, b1) \
    asm volatile("mma.sync.aligned.m16n8k16.row.col.f32.f16.f16.f32 " \
        "{%0,%1,%2,%3}, {%4,%5,%6,%7}, {%8,%9}, {%0,%1,%2,%3};" \
        : "+f"((c)[0]), "+f"((c)[1]), "+f"((c)[2]), "+f"((c)[3]) \
        : "r"((a)[0]), "r"((a)[1]), "r"((a)[2]), "r"((a)[3]), "r"(b0), "r"(b1))

__device__ __forceinline__ uint32_t packh2(float lo, float hi) {
    __half2 h = __floats2half2_rn(lo, hi);
    return *(uint32_t*)&h;
}
__device__ __forceinline__ float ex2f(float x) {
    float r;
    asm("ex2.approx.f32 %0, %1;" : "=f"(r) : "f"(x));
    return r;
}

// ---------------- problem mapping ----------------
__device__ __forceinline__ int hilbert_p(int index, int d) {
    int x = 0, y = 0;
    for (int s = 1; s < d; s <<= 1) {
        int rx = 1 & (index >> 1);
        int ry = 1 & (index ^ rx);
        if (ry == 0) {
            if (rx == 1) { int nx = s - 1 - y; int ny = s - 1 - x; x = nx; y = ny; }
            int t = x; x = y; y = t;
        }
        x += s * rx;
        y += s * ry;
        index >>= 2;
    }
    return x * d + y;
}
__device__ __forceinline__ void decode_slot(int s, int& grp, int& head, int& qbase) {
    if (s < 20)      { grp = 0; head = s % 5;                     qbase = (s / 5) * 2048; }
    else if (s < 30) { grp = 1; int r = s - 20; head = 5 + r % 5; qbase = (r / 5) * 4096; }
    else             { grp = 2; head = 10 + (s - 30);             qbase = 0; }
}
__device__ __forceinline__ int kv_pos(int grp, int j) {
    if (grp == 0) return j;
    if (grp == 1) return hilbert_p(2 * j, 64);
    return hilbert_p(4 * j, 128);
}
__device__ __forceinline__ int qrow_base(int slot) {
    if (slot < 20) return slot * 2048;
    if (slot < 30) return 40960 + (slot - 20) * 4096;
    return 81920 + (slot - 30) * 8192;
}

// ---- mega-gather: K | zero head15 | Q | V-transpose (4 block ranges) ----
__global__ void gather_all_kernel(const float* __restrict__ k,
                                  const float* __restrict__ q,
                                  const float* __restrict__ v,
                                  float* __restrict__ out) {
    __shared__ float t[64][132];   // used only by the V range
    if (blockIdx.x < 4480) {          // ---- K gather ----
        int idx  = blockIdx.x * blockDim.x + threadIdx.x;
        int slot = idx >> 15;
        int rem  = idx & 32767;
        int row  = rem >> 4;
        int q4   = rem & 15;
        int grp, head, qbase;
        decode_slot(slot, grp, head, qbase);
        int pos = qbase + kv_pos(grp, row);
        float4 kv = *(const float4*)(k + ((size_t)pos * HEADS + head) * HDIM + q4 * 4);
        __half* dst = g_K + ((size_t)slot * NK + row) * HDIM + q4 * 4;
        *(__half2*)(dst)     = __floats2half2_rn(kv.x, kv.y);
        *(__half2*)(dst + 2) = __floats2half2_rn(kv.z, kv.w);
    } else if (blockIdx.x < 4992) {   // ---- zero head-15 ----
        int tt  = (blockIdx.x - 4480) * blockDim.x + threadIdx.x;
        int pos = tt >> 4;
        int d4  = tt & 15;
        *(float4*)(out + (size_t)pos * (HEADS * HDIM) + 15 * HDIM + d4 * 4) =
            make_float4(0.f, 0.f, 0.f, 0.f);
    } else if (blockIdx.x < 12672) {  // ---- Q gather (scaled) ----
        int idx  = (blockIdx.x - 4992) * blockDim.x + threadIdx.x;
        int srow = idx >> 4;
        int q4   = idx & 15;
        int slot, local;
        if (srow < 40960)      { slot = srow >> 11;                  local = srow & 2047; }
        else if (srow < 81920) { slot = 20 + ((srow - 40960) >> 12); local = (srow - 40960) & 4095; }
        else                   { slot = 30 + ((srow - 81920) >> 13); local = (srow - 81920) & 8191; }
        int grp, head, qbase;
        decode_slot(slot, grp, head, qbase);
        int pos = qbase + local;
        float4 qv = *(const float4*)(q + ((size_t)pos * HEADS + head) * HDIM + q4 * 4);
        __half* dst = g_Q + (size_t)srow * HDIM + q4 * 4;
        *(__half2*)(dst)     = __floats2half2_rn(qv.x * QSCALE_LOG2E, qv.y * QSCALE_LOG2E);
        *(__half2*)(dst + 2) = __floats2half2_rn(qv.z * QSCALE_LOG2E, qv.w * QSCALE_LOG2E);
    } else {                          // ---- V transpose-gather ----
        int b    = blockIdx.x - 12672;
        int slot = b >> 4;
        int kt   = b & 15;
        int grp, head, qbase;
        decode_slot(slot, grp, head, qbase);
        int tid = threadIdx.x;
        #pragma unroll
        for (int it = 0; it < 8; ++it) {
            int idx = it * 256 + tid;
            int key = idx >> 4;
            int c   = (idx & 15) * 4;
            int pos = qbase + kv_pos(grp, kt * 128 + key);
            float4 vv = *(const float4*)(v + ((size_t)pos * HEADS + head) * HDIM + c);
            t[c + 0][key] = vv.x;
            t[c + 1][key] = vv.y;
            t[c + 2][key] = vv.z;
            t[c + 3][key] = vv.w;
        }
        __syncthreads();
        #pragma unroll
        for (int it = 0; it < 8; ++it) {
            int idx = it * 256 + tid;
            int d   = idx >> 5;
            int c4  = (idx & 31) * 4;
            __half* dst = g_V + ((size_t)slot * HDIM + d) * NK + kt * 128 + c4;
            *(__half2*)(dst)     = __floats2half2_rn(t[d][c4],     t[d][c4 + 1]);
            *(__half2*)(dst + 2) = __floats2half2_rn(t[d][c4 + 2], t[d][c4 + 3]);
        }
    }
}

// ------- attention: 128 threads, 4 warps x m32, 2 CTAs/SM, lean sw-pipeline -------
__device__ __forceinline__ void prefetch_tile(uint32_t sb, int buf, int slot, int kt, int tid) {
    #pragma unroll
    for (int it = 0; it < 8; ++it) {
        int idx = it * 128 + tid;
        int row = idx >> 3;
        int c16 = idx & 7;
        uint32_t dst = sb + KS_OFF(buf) + row * 128 + (((c16 ^ (row & 7))) << 4);
        const void* src = g_K + ((size_t)(slot * NK + kt * 128 + row)) * HDIM + c16 * 8;
        CP_ASYNC16(dst, src);
    }
    #pragma unroll
    for (int it = 0; it < 8; ++it) {
        int idx = it * 128 + tid;
        int row = idx >> 4;
        int c16 = idx & 15;
        uint32_t dst = sb + VS_OFF(buf) + row * 256 + (((c16 ^ (row & 7))) << 4);
        const void* src = g_V + ((size_t)slot * HDIM + row) * NK + kt * 128 + c16 * 8;
        CP_ASYNC16(dst, src);
    }
}

// ---- pipeline stages: SINGLE S set, SINGLE pa set (fits in regs) ----
__device__ __forceinline__ void qk_chunk(uint32_t kbase, int ch, int hb, int l7, int lane,
                                         uint32_t aQ[2][4][4],
                                         float S0[4][4], float S1[4][4]) {
    #pragma unroll
    for (int i = 0; i < 4; ++i)
        #pragma unroll
        for (int j = 0; j < 4; ++j) { S0[i][j] = 0.f; S1[i][j] = 0.f; }
    #pragma unroll
    for (int kk = 0; kk < 4; ++kk) {
        int c16 = 2 * kk + hb;
        uint32_t colp = ((uint32_t)(c16 ^ l7)) << 4;
        #pragma unroll
        for (int j = 0; j < 2; ++j) {
            int nn2 = 2 * ch + j;
            int row = 16 * nn2 + 8 * (lane >> 4) + l7;
            uint32_t addr = kbase + row * 128 + colp;
            uint32_t b0, b1, b2, b3;
            LDSM_X4(b0, b1, b2, b3, addr);
            MMA_FP16(S0[2 * j],     aQ[0][kk], b0, b1);
            MMA_FP16(S0[2 * j + 1], aQ[0][kk], b2, b3);
            MMA_FP16(S1[2 * j],     aQ[1][kk], b0, b1);
            MMA_FP16(S1[2 * j + 1], aQ[1][kk], b2, b3);
        }
    }
}

__device__ __forceinline__ void ex2_chunk(float S0[4][4], float S1[4][4],
                                          uint32_t pa0[2][4], uint32_t pa1[2][4],
                                          float& ls00, float& ls01,
                                          float& ls10, float& ls11) {
    #pragma unroll
    for (int t = 0; t < 4; ++t) {
        int kx = t >> 1, o = (t & 1) * 2;
        float p0 = ex2f(S0[t][0]), p1 = ex2f(S0[t][1]);
        float p2 = ex2f(S0[t][2]), p3 = ex2f(S0[t][3]);
        ls00 += p0 + p1; ls01 += p2 + p3;
        pa0[kx][o] = packh2(p0, p1); pa0[kx][o + 1] = packh2(p2, p3);
        float r0 = ex2f(S1[t][0]), r1 = ex2f(S1[t][1]);
        float r2 = ex2f(S1[t][2]), r3 = ex2f(S1[t][3]);
        ls10 += r0 + r1; ls11 += r2 + r3;
        pa1[kx][o] = packh2(r0, r1); pa1[kx][o + 1] = packh2(r2, r3);
    }
}

__device__ __forceinline__ void pv_chunk(uint32_t vbase, int ch, int hb, int l7, int lane,
                                         uint32_t pa0[2][4], uint32_t pa1[2][4],
                                         float O0[8][4], float O1[8][4]) {
    #pragma unroll
    for (int kx = 0; kx < 2; ++kx) {
        int c16 = 2 * (2 * ch + kx) + hb;
        uint32_t colp = ((uint32_t)(c16 ^ l7)) << 4;
        #pragma unroll
        for (int nd2 = 0; nd2 < 4; ++nd2) {
            int row = 16 * nd2 + 8 * (lane >> 4) + l7;
            uint32_t addr = vbase + row * 256 + colp;
            uint32_t b0, b1, b2, b3;
            LDSM_X4(b0, b1, b2, b3, addr);
            MMA_FP16(O0[2 * nd2],     pa0[kx], b0, b1);
            MMA_FP16(O0[2 * nd2 + 1], pa0[kx], b2, b3);
            MMA_FP16(O1[2 * nd2],     pa1[kx], b0, b1);
            MMA_FP16(O1[2 * nd2 + 1], pa1[kx], b2, b3);
        }
    }
}

__global__ void __launch_bounds__(128, 2)
attn_kernel(float* __restrict__ out) {
    int bx = blockIdx.x;
    int slot, tile;
    if (bx < 320)      { slot = bx >> 4;               tile = bx & 15; }
    else if (bx < 640) { int r = bx - 320; slot = 20 + (r >> 5); tile = r & 31; }
    else               { int r = bx - 640; slot = 30 + (r >> 6); tile = r & 63; }
    int grp, head, qbase;
    decode_slot(slot, grp, head, qbase);
    int q0   = qbase + tile * 128;
    int qrow = qrow_base(slot) + tile * 128;

    extern __shared__ __align__(1024) char smem[];
    uint32_t sb = smem_u32(smem);
    int tid  = threadIdx.x;
    int lane = tid & 31;
    int w    = tid >> 5;
    int l7   = lane & 7;
    int hb   = (lane >> 3) & 1;
    int g    = lane >> 2;
    int t4   = lane & 3;

    #pragma unroll
    for (int it = 0; it < 8; ++it) {
        int idx = it * 128 + tid;
        int row = idx >> 3;
        int c16 = idx & 7;
        uint32_t dst = sb + QS_OFF + row * 128 + ((c16 ^ (row & 7)) << 4);
        const void* src = g_Q + (size_t)(qrow + row) * HDIM + c16 * 8;
        CP_ASYNC16(dst, src);
    }
    prefetch_tile(sb, 0, slot, 0, tid);
    CP_COMMIT();
    prefetch_tile(sb, 1, slot, 1, tid);
    CP_COMMIT();

    uint32_t aQ[2][4][4];
    float O0[8][4], O1[8][4];
    #pragma unroll
    for (int i = 0; i < 8; ++i)
        #pragma unroll
        for (int j = 0; j < 4; ++j) { O0[i][j] = 0.f; O1[i][j] = 0.f; }
    float ls00 = 0.f, ls01 = 0.f, ls10 = 0.f, ls11 = 0.f;

    int buf = 0;
    for (int kt = 0; kt < 16; ++kt) {
        if (kt == 15) { CP_WAIT_0(); } else { CP_WAIT_1(); }
        __syncthreads();

        if (kt == 0) {
            #pragma unroll
            for (int ms = 0; ms < 2; ++ms)
                #pragma unroll
                for (int kk = 0; kk < 4; ++kk) {
                    int row = w * 32 + ms * 16 + (lane & 15);
                    int c16 = 2 * kk + (lane >> 4);
                    uint32_t a = sb + QS_OFF + row * 128 + ((c16 ^ (row & 7)) << 4);
                    LDSM_X4(aQ[ms][kk][0], aQ[ms][kk][1], aQ[ms][kk][2], aQ[ms][kk][3], a);
                }
        }

        uint32_t kbase = sb + KS_OFF(buf);
        uint32_t vbase = sb + VS_OFF(buf);

        // lean rotation: qk(0); e(0); { qk(ch+1); pv(ch); e(ch+1) } x3; pv(3)
        // (single S, single pa — EX2->PV gap bridged by the next QK chunk)
        float S0[4][4], S1[4][4];
        uint32_t pa0[2][4], pa1[2][4];

        qk_chunk(kbase, 0, hb, l7, lane, aQ, S0, S1);
        ex2_chunk(S0, S1, pa0, pa1, ls00, ls01, ls10, ls11);
        #pragma unroll
        for (int ch = 0; ch < 3; ++ch) {
            qk_chunk(kbase, ch + 1, hb, l7, lane, aQ, S0, S1);
            pv_chunk(vbase, ch, hb, l7, lane, pa0, pa1, O0, O1);
            ex2_chunk(S0, S1, pa0, pa1, ls00, ls01, ls10, ls11);
        }
        pv_chunk(vbase, 3, hb, l7, lane, pa0, pa1, O0, O1);

        if (kt <= 13) {
            int nb = buf + 2; if (nb >= 3) nb -= 3;
            prefetch_tile(sb, nb, slot, kt + 2, tid);
            CP_COMMIT();
        }
        if (++buf == 3) buf = 0;
    }

    // ---- epilogue ----
    #pragma unroll
    for (int o = 1; o <= 2; o <<= 1) {
        ls00 += __shfl_xor_sync(0xffffffffu, ls00, o);
        ls01 += __shfl_xor_sync(0xffffffffu, ls01, o);
        ls10 += __shfl_xor_sync(0xffffffffu, ls10, o);
        ls11 += __shfl_xor_sync(0xffffffffu, ls11, o);
    }
    float i00 = 1.f / ls00, i01 = 1.f / ls01, i10 = 1.f / ls10, i11 = 1.f / ls11;

    int r00 = q0 + w * 32 + g;
    float* o00 = out + ((size_t)r00 * HEADS + head) * HDIM;
    float* o01 = out + ((size_t)(r00 + 8) * HEADS + head) * HDIM;
    float* o10 = out + ((size_t)(r00 + 16) * HEADS + head) * HDIM;
    float* o11 = out + ((size_t)(r00 + 24) * HEADS + head) * HDIM;
    #pragma unroll
    for (int nd = 0; nd < 8; ++nd) {
        int d = nd * 8 + t4 * 2;
        *(float2*)(o00 + d) = make_float2(O0[nd][0] * i00, O0[nd][1] * i00);
        *(float2*)(o01 + d) = make_float2(O0[nd][2] * i01, O0[nd][3] * i01);
        *(float2*)(o10 + d) = make_float2(O1[nd][0] * i10, O1[nd][1] * i10);
        *(float2*)(o11 + d) = make_float2(O1[nd][2] * i11, O1[nd][3] * i11);
    }
}

extern "C" void kernel_launch(void* const* d_in, const int* in_sizes, int n_in,
                              void* d_out, int out_size) {
    (void)in_sizes; (void)n_in; (void)out_size;
    const float* q = (const float*)d_in[0];
    const float* k = (const float*)d_in[1];
    const float* v = (const float*)d_in[2];
    float* out = (float*)d_out;

    cudaFuncSetAttribute(attn_kernel,
                         cudaFuncAttributeMaxDynamicSharedMemorySize, SMEM_BYTES);

    gather_all_kernel<<<13232, 256>>>(k, q, v, out);  // K | head15 | Q | V
    attn_kernel<<<960, 128, SMEM_BYTES>>>(out);
}

// round 14
// speedup vs baseline: 1.0241x; 1.0241x over previous
#include <cuda_runtime.h>
#include <cuda_fp16.h>
#include <cstdint>

#define HEADS   16
#define HDIM    64
#define NK      2048
#define NSLOT   35
#define NQROWS  122880     // 20*2048 + 10*4096 + 5*8192
// 0.125 (d^-0.5) * log2(e) folded into Q so softmax is exp2(s)
#define QSCALE_LOG2E 0.1803368801111f

__device__ __half g_Q[NQROWS * HDIM];
__device__ __half g_K[NSLOT * NK * HDIM];
__device__ __half g_V[NSLOT * HDIM * NK];

// smem: Q[128][64] fp16 (16KB) | K x3 [128][64] (48KB) | Vt x3 [64][128] (48KB)
#define QS_OFF    0
#define KS_OFF(b) (16384 + (b) * 16384)
#define VS_OFF(b) (65536 + (b) * 16384)
#define SMEM_BYTES 114688

// ---------------- PTX helpers ----------------
__device__ __forceinline__ uint32_t smem_u32(const void* p) {
    uint32_t a;
    asm("{ .reg .u64 t; cvta.to.shared.u64 t, %1; cvt.u32.u64 %0, t; }" : "=r"(a) : "l"(p));
    return a;
}
#define CP_ASYNC16(dst, src) \
    asm volatile("cp.async.cg.shared.global [%0], [%1], 16;" :: "r"(dst), "l"(src) : "memory")
#define CP_COMMIT()  asm volatile("cp.async.commit_group;" ::: "memory")
#define CP_WAIT_1()  asm volatile("cp.async.wait_group 1;" ::: "memory")
#define CP_WAIT_0()  asm volatile("cp.async.wait_group 0;" ::: "memory")

#define LDSM_X4(r0, r1, r2, r3, addr) \
    asm volatile("ldmatrix.sync.aligned.m8n8.x4.shared.b16 {%0,%1,%2,%3}, [%4];" \
        : "=r"(r0), "=r"(r1), "=r"(r2), "=r"(r3) : "r"(addr))

#define MMA_FP16(c, a, b0, b1) \
    asm volatile("mma.sync.aligned.m16n8k16.row.col.f32.f16.f16.f32 " \
        "{%0,%1,%2,%3}, {%4,%5,%6,%7}, {%8,%9}, {%0,%1,%2,%3};" \
        : "+f"((c)[0]), "+f"((c)[1]), "+f"((c)[2]), "+f"((c)[3]) \
        : "r"((a)[0]), "r"((a)[1]), "r"((a)[2]), "r"((a)[3]), "r"(b0), "r"(b1))

__device__ __forceinline__ uint32_t packh2(float lo, float hi) {
    __half2 h = __floats2half2_rn(lo, hi);
    return *(uint32_t*)&h;
}

// ---------------- problem mapping ----------------
__device__ __forceinline__ int hilbert_p(int index, int d) {
    int x = 0, y = 0;
    for (int s = 1; s < d; s <<= 1) {
        int rx = 1 & (index >> 1);
        int ry = 1 & (index ^ rx);
        if (ry == 0) {
            if (rx == 1) { int nx = s - 1 - y; int ny = s - 1 - x; x = nx; y = ny; }
            int t = x; x = y; y = t;
        }
        x += s * rx;
        y += s * ry;
        index >>= 2;
    }
    return x * d + y;
}
__device__ __forceinline__ void decode_slot(int s, int& grp, int& head, int& qbase) {
    if (s < 20)      { grp = 0; head = s % 5;                     qbase = (s / 5) * 2048; }
    else if (s < 30) { grp = 1; int r = s - 20; head = 5 + r % 5; qbase = (r / 5) * 4096; }
    else             { grp = 2; head = 10 + (s - 30);             qbase = 0; }
}
__device__ __forceinline__ int kv_pos(int grp, int j) {
    if (grp == 0) return j;
    if (grp == 1) return hilbert_p(2 * j, 64);
    return hilbert_p(4 * j, 128);
}
__device__ __forceinline__ int qrow_base(int slot) {
    if (slot < 20) return slot * 2048;
    if (slot < 30) return 40960 + (slot - 20) * 4096;
    return 81920 + (slot - 30) * 8192;
}

// ---- mega-gather: K | zero head15 | Q | V-transpose (4 block ranges) ----
__global__ void gather_all_kernel(const float* __restrict__ k,
                                  const float* __restrict__ q,
                                  const float* __restrict__ v,
                                  float* __restrict__ out) {
    __shared__ float t[64][132];   // used only by the V range
    if (blockIdx.x < 4480) {          // ---- K gather ----
        int idx  = blockIdx.x * blockDim.x + threadIdx.x;
        int slot = idx >> 15;
        int rem  = idx & 32767;
        int row  = rem >> 4;
        int q4   = rem & 15;
        int grp, head, qbase;
        decode_slot(slot, grp, head, qbase);
        int pos = qbase + kv_pos(grp, row);
        float4 kv = *(const float4*)(k + ((size_t)pos * HEADS + head) * HDIM + q4 * 4);
        __half* dst = g_K + ((size_t)slot * NK + row) * HDIM + q4 * 4;
        *(__half2*)(dst)     = __floats2half2_rn(kv.x, kv.y);
        *(__half2*)(dst + 2) = __floats2half2_rn(kv.z, kv.w);
    } else if (blockIdx.x < 4992) {   // ---- zero head-15 ----
        int tt  = (blockIdx.x - 4480) * blockDim.x + threadIdx.x;
        int pos = tt >> 4;
        int d4  = tt & 15;
        *(float4*)(out + (size_t)pos * (HEADS * HDIM) + 15 * HDIM + d4 * 4) =
            make_float4(0.f, 0.f, 0.f, 0.f);
    } else if (blockIdx.x < 12672) {  // ---- Q gather (scaled) ----
        int idx  = (blockIdx.x - 4992) * blockDim.x + threadIdx.x;
        int srow = idx >> 4;
        int q4   = idx & 15;
        int slot, local;
        if (srow < 40960)      { slot = srow >> 11;                  local = srow & 2047; }
        else if (srow < 81920) { slot = 20 + ((srow - 40960) >> 12); local = (srow - 40960) & 4095; }
        else                   { slot = 30 + ((srow - 81920) >> 13); local = (srow - 81920) & 8191; }
        int grp, head, qbase;
        decode_slot(slot, grp, head, qbase);
        int pos = qbase + local;
        float4 qv = *(const float4*)(q + ((size_t)pos * HEADS + head) * HDIM + q4 * 4);
        __half* dst = g_Q + (size_t)srow * HDIM + q4 * 4;
        *(__half2*)(dst)     = __floats2half2_rn(qv.x * QSCALE_LOG2E, qv.y * QSCALE_LOG2E);
        *(__half2*)(dst + 2) = __floats2half2_rn(qv.z * QSCALE_LOG2E, qv.w * QSCALE_LOG2E);
    } else {                          // ---- V transpose-gather ----
        int b    = blockIdx.x - 12672;
        int slot = b >> 4;
        int kt   = b & 15;
        int grp, head, qbase;
        decode_slot(slot, grp, head, qbase);
        int tid = threadIdx.x;
        #pragma unroll
        for (int it = 0; it < 8; ++it) {
            int idx = it * 256 + tid;
            int key = idx >> 4;
            int c   = (idx & 15) * 4;
            int pos = qbase + kv_pos(grp, kt * 128 + key);
            float4 vv = *(const float4*)(v + ((size_t)pos * HEADS + head) * HDIM + c);
            t[c + 0][key] = vv.x;
            t[c + 1][key] = vv.y;
            t[c + 2][key] = vv.z;
            t[c + 3][key] = vv.w;
        }
        __syncthreads();
        #pragma unroll
        for (int it = 0; it < 8; ++it) {
            int idx = it * 256 + tid;
            int d   = idx >> 5;
            int c4  = (idx & 31) * 4;
            __half* dst = g_V + ((size_t)slot * HDIM + d) * NK + kt * 128 + c4;
            *(__half2*)(dst)     = __floats2half2_rn(t[d][c4],     t[d][c4 + 1]);
            *(__half2*)(dst + 2) = __floats2half2_rn(t[d][c4 + 2], t[d][c4 + 3]);
        }
    }
}

// ------- attention: 128 threads, 4 warps x m32, 2 CTAs/SM -------
__device__ __forceinline__ void prefetch_tile(uint32_t sb, int buf, int slot, int kt, int tid) {
    #pragma unroll
    for (int it = 0; it < 8; ++it) {
        int idx = it * 128 + tid;
        int row = idx >> 3;
        int c16 = idx & 7;
        uint32_t dst = sb + KS_OFF(buf) + row * 128 + (((c16 ^ (row & 7))) << 4);
        const void* src = g_K + ((size_t)(slot * NK + kt * 128 + row)) * HDIM + c16 * 8;
        CP_ASYNC16(dst, src);
    }
    #pragma unroll
    for (int it = 0; it < 8; ++it) {
        int idx = it * 128 + tid;
        int row = idx >> 4;
        int c16 = idx & 15;
        uint32_t dst = sb + VS_OFF(buf) + row * 256 + (((c16 ^ (row & 7))) << 4);
        const void* src = g_V + ((size_t)slot * HDIM + row) * NK + kt * 128 + c16 * 8;
        CP_ASYNC16(dst, src);
    }
}

// ---- pipeline stages ----
__device__ __forceinline__ void qk_chunk(uint32_t kbase, int ch, int hb, int l7, int lane,
                                         uint32_t aQ[2][4][4],
                                         float S0[4][4], float S1[4][4]) {
    #pragma unroll
    for (int i = 0; i < 4; ++i)
        #pragma unroll
        for (int j = 0; j < 4; ++j) { S0[i][j] = 0.f; S1[i][j] = 0.f; }
    #pragma unroll
    for (int kk = 0; kk < 4; ++kk) {
        int c16 = 2 * kk + hb;
        uint32_t colp = ((uint32_t)(c16 ^ l7)) << 4;
        #pragma unroll
        for (int j = 0; j < 2; ++j) {
            int nn2 = 2 * ch + j;
            int row = 16 * nn2 + 8 * (lane >> 4) + l7;
            uint32_t addr = kbase + row * 128 + colp;
            uint32_t b0, b1, b2, b3;
            LDSM_X4(b0, b1, b2, b3, addr);
            MMA_FP16(S0[2 * j],     aQ[0][kk], b0, b1);
            MMA_FP16(S0[2 * j + 1], aQ[0][kk], b2, b3);
            MMA_FP16(S1[2 * j],     aQ[1][kk], b0, b1);
            MMA_FP16(S1[2 * j + 1], aQ[1][kk], b2, b3);
        }
    }
}

// VOLATILE ex2, in place — pinned BEFORE the next chunk's (volatile) MMAs so
// the MUFU drain overlaps tensor work instead of stalling the warp.
__device__ __forceinline__ void ex2_issue(float S0[4][4], float S1[4][4]) {
    #pragma unroll
    for (int t = 0; t < 4; ++t)
        #pragma unroll
        for (int j = 0; j < 4; ++j) {
            asm volatile("ex2.approx.f32 %0, %0;" : "+f"(S0[t][j]));
            asm volatile("ex2.approx.f32 %0, %0;" : "+f"(S1[t][j]));
        }
}

// pack exp'ed S -> fp16 pa fragments + lsum accumulation (no MUFU here)
__device__ __forceinline__ void pack_chunk(float S0[4][4], float S1[4][4],
                                           uint32_t pa0[2][4], uint32_t pa1[2][4],
                                           float& ls00, float& ls01,
                                           float& ls10, float& ls11) {
    #pragma unroll
    for (int t = 0; t < 4; ++t) {
        int kx = t >> 1, o = (t & 1) * 2;
        ls00 += S0[t][0] + S0[t][1];
        ls01 += S0[t][2] + S0[t][3];
        pa0[kx][o]     = packh2(S0[t][0], S0[t][1]);
        pa0[kx][o + 1] = packh2(S0[t][2], S0[t][3]);
        ls10 += S1[t][0] + S1[t][1];
        ls11 += S1[t][2] + S1[t][3];
        pa1[kx][o]     = packh2(S1[t][0], S1[t][1]);
        pa1[kx][o + 1] = packh2(S1[t][2], S1[t][3]);
    }
}

__device__ __forceinline__ void pv_chunk(uint32_t vbase, int ch, int hb, int l7, int lane,
                                         uint32_t pa0[2][4], uint32_t pa1[2][4],
                                         float O0[8][4], float O1[8][4]) {
    #pragma unroll
    for (int kx = 0; kx < 2; ++kx) {
        int c16 = 2 * (2 * ch + kx) + hb;
        uint32_t colp = ((uint32_t)(c16 ^ l7)) << 4;
        #pragma unroll
        for (int nd2 = 0; nd2 < 4; ++nd2) {
            int row = 16 * nd2 + 8 * (lane >> 4) + l7;
            uint32_t addr = vbase + row * 256 + colp;
            uint32_t b0, b1, b2, b3;
            LDSM_X4(b0, b1, b2, b3, addr);
            MMA_FP16(O0[2 * nd2],     pa0[kx], b0, b1);
            MMA_FP16(O0[2 * nd2 + 1], pa0[kx], b2, b3);
            MMA_FP16(O1[2 * nd2],     pa1[kx], b0, b1);
            MMA_FP16(O1[2 * nd2 + 1], pa1[kx], b2, b3);
        }
    }
}

__global__ void __launch_bounds__(128, 2)
attn_kernel(float* __restrict__ out) {
    int bx = blockIdx.x;
    int slot, tile;
    if (bx < 320)      { slot = bx >> 4;               tile = bx & 15; }
    else if (bx < 640) { int r = bx - 320; slot = 20 + (r >> 5); tile = r & 31; }
    else               { int r = bx - 640; slot = 30 + (r >> 6); tile = r & 63; }
    int grp, head, qbase;
    decode_slot(slot, grp, head, qbase);
    int q0   = qbase + tile * 128;
    int qrow = qrow_base(slot) + tile * 128;

    extern __shared__ __align__(1024) char smem[];
    uint32_t sb = smem_u32(smem);
    int tid  = threadIdx.x;
    int lane = tid & 31;
    int w    = tid >> 5;
    int l7   = lane & 7;
    int hb   = (lane >> 3) & 1;
    int g    = lane >> 2;
    int t4   = lane & 3;

    #pragma unroll
    for (int it = 0; it < 8; ++it) {
        int idx = it * 128 + tid;
        int row = idx >> 3;
        int c16 = idx & 7;
        uint32_t dst = sb + QS_OFF + row * 128 + ((c16 ^ (row & 7)) << 4);
        const void* src = g_Q + (size_t)(qrow + row) * HDIM + c16 * 8;
        CP_ASYNC16(dst, src);
    }
    prefetch_tile(sb, 0, slot, 0, tid);
    CP_COMMIT();
    prefetch_tile(sb, 1, slot, 1, tid);
    CP_COMMIT();

    uint32_t aQ[2][4][4];
    float O0[8][4], O1[8][4];
    #pragma unroll
    for (int i = 0; i < 8; ++i)
        #pragma unroll
        for (int j = 0; j < 4; ++j) { O0[i][j] = 0.f; O1[i][j] = 0.f; }
    float ls00 = 0.f, ls01 = 0.f, ls10 = 0.f, ls11 = 0.f;

    int buf = 0;
    for (int kt = 0; kt < 16; ++kt) {
        if (kt == 15) { CP_WAIT_0(); } else { CP_WAIT_1(); }
        __syncthreads();

        if (kt == 0) {
            #pragma unroll
            for (int ms = 0; ms < 2; ++ms)
                #pragma unroll
                for (int kk = 0; kk < 4; ++kk) {
                    int row = w * 32 + ms * 16 + (lane & 15);
                    int c16 = 2 * kk + (lane >> 4);
                    uint32_t a = sb + QS_OFF + row * 128 + ((c16 ^ (row & 7)) << 4);
                    LDSM_X4(aQ[ms][kk][0], aQ[ms][kk][1], aQ[ms][kk][2], aQ[ms][kk][3], a);
                }
        }

        uint32_t kbase = sb + KS_OFF(buf);
        uint32_t vbase = sb + VS_OFF(buf);

        // forced-overlap schedule (volatile EX2 pinned before next qk's MMAs):
        // qk(0,Sa) e(Sa) | qk(1,Sb) pack(Sa) pv(0) e(Sb) | qk(2,Sa) pack(Sb) pv(1) e(Sa)
        //               | qk(3,Sb) pack(Sa) pv(2) e(Sb) | pack(Sb) pv(3)
        float Sa0[4][4], Sa1[4][4], Sb0[4][4], Sb1[4][4];
        uint32_t pa0[2][4], pa1[2][4];

        qk_chunk(kbase, 0, hb, l7, lane, aQ, Sa0, Sa1);
        ex2_issue(Sa0, Sa1);

        qk_chunk(kbase, 1, hb, l7, lane, aQ, Sb0, Sb1);
        pack_chunk(Sa0, Sa1, pa0, pa1, ls00, ls01, ls10, ls11);
        pv_chunk(vbase, 0, hb, l7, lane, pa0, pa1, O0, O1);
        ex2_issue(Sb0, Sb1);

        qk_chunk(kbase, 2, hb, l7, lane, aQ, Sa0, Sa1);
        pack_chunk(Sb0, Sb1, pa0, pa1, ls00, ls01, ls10, ls11);
        pv_chunk(vbase, 1, hb, l7, lane, pa0, pa1, O0, O1);
        ex2_issue(Sa0, Sa1);

        qk_chunk(kbase, 3, hb, l7, lane, aQ, Sb0, Sb1);
        pack_chunk(Sa0, Sa1, pa0, pa1, ls00, ls01, ls10, ls11);
        pv_chunk(vbase, 2, hb, l7, lane, pa0, pa1, O0, O1);
        ex2_issue(Sb0, Sb1);

        pack_chunk(Sb0, Sb1, pa0, pa1, ls00, ls01, ls10, ls11);
        pv_chunk(vbase, 3, hb, l7, lane, pa0, pa1, O0, O1);

        if (kt <= 13) {
            int nb = buf + 2; if (nb >= 3) nb -= 3;
            prefetch_tile(sb, nb, slot, kt + 2, tid);
            CP_COMMIT();
        }
        if (++buf == 3) buf = 0;
    }

    // ---- epilogue ----
    #pragma unroll
    for (int o = 1; o <= 2; o <<= 1) {
        ls00 += __shfl_xor_sync(0xffffffffu, ls00, o);
        ls01 += __shfl_xor_sync(0xffffffffu, ls01, o);
        ls10 += __shfl_xor_sync(0xffffffffu, ls10, o);
        ls11 += __shfl_xor_sync(0xffffffffu, ls11, o);
    }
    float i00 = 1.f / ls00, i01 = 1.f / ls01, i10 = 1.f / ls10, i11 = 1.f / ls11;

    int r00 = q0 + w * 32 + g;
    float* o00 = out + ((size_t)r00 * HEADS + head) * HDIM;
    float* o01 = out + ((size_t)(r00 + 8) * HEADS + head) * HDIM;
    float* o10 = out + ((size_t)(r00 + 16) * HEADS + head) * HDIM;
    float* o11 = out + ((size_t)(r00 + 24) * HEADS + head) * HDIM;
    #pragma unroll
    for (int nd = 0; nd < 8; ++nd) {
        int d = nd * 8 + t4 * 2;
        *(float2*)(o00 + d) = make_float2(O0[nd][0] * i00, O0[nd][1] * i00);
        *(float2*)(o01 + d) = make_float2(O0[nd][2] * i01, O0[nd][3] * i01);
        *(float2*)(o10 + d) = make_float2(O1[nd][0] * i10, O1[nd][1] * i10);
        *(float2*)(o11 + d) = make_float2(O1[nd][2] * i11, O1[nd][3] * i11);
    }
}

extern "C" void kernel_launch(void* const* d_in, const int* in_sizes, int n_in,
                              void* d_out, int out_size) {
    (void)in_sizes; (void)n_in; (void)out_size;
    const float* q = (const float*)d_in[0];
    const float* k = (const float*)d_in[1];
    const float* v = (const float*)d_in[2];
    float* out = (float*)d_out;

    cudaFuncSetAttribute(attn_kernel,
                         cudaFuncAttributeMaxDynamicSharedMemorySize, SMEM_BYTES);

    gather_all_kernel<<<13232, 256>>>(k, q, v, out);  // K | head15 | Q | V
    attn_kernel<<<960, 128, SMEM_BYTES>>>(out);
}